// round 15
// baseline (speedup 1.0000x reference)
#include <cuda_runtime.h>
#include <cuda_fp16.h>
#include <mma.h>
#include <math.h>

using namespace nvcuda;

// GraphSAGE 3-layer, N=100000, E=3200000, D: 64 -> 64 -> 32 -> 1
// CSR gather + wmma dense chain.
// R14: warp-per-node gathers with multi-edge lanes (zero degree divergence).

#define NMAX 100000
#define NPAD 100096
#define EMAX 3200000
#define SCAN_TB 1024

__device__ __align__(16) __half2 g_xh[NPAD * 32];   // x in fp16 (64 per node)
__device__ __align__(16) __half2 g_mh[NPAD * 32];   // layer-1 mean in fp16
__device__ __align__(16) __half2 g_p2[NPAD * 16];   // h1@W2l in fp16 (32 per node)
__device__ __align__(16) float   g_r2[NMAX * 32];   // h1@W2r in fp32 (self term)
__device__ __half g_W1lh[64 * 64];
__device__ __half g_W1rh[64 * 64];
__device__ __half g_W2lh[64 * 32];
__device__ __half g_W2rh[64 * 32];
__device__ float g_p3[NMAX];
__device__ float g_r3[NMAX];
__device__ float g_inv[NMAX];
__device__ int   g_deg[NMAX];
__device__ int   g_start[NMAX];
__device__ int   g_fill[NMAX];
__device__ int   g_bsum[128];
__device__ int   g_csr[EMAX];

// ---------------- CSR build ----------------

__global__ void hist_kernel(const int* __restrict__ dst, int E) {
    int t = blockIdx.x * blockDim.x + threadIdx.x;
    int e = t * 8;
    if (e + 8 <= E) {
        int4 d0 = *(const int4*)(dst + e);
        int4 d1 = *(const int4*)(dst + e + 4);
        atomicAdd(&g_deg[d0.x], 1);
        atomicAdd(&g_deg[d0.y], 1);
        atomicAdd(&g_deg[d0.z], 1);
        atomicAdd(&g_deg[d0.w], 1);
        atomicAdd(&g_deg[d1.x], 1);
        atomicAdd(&g_deg[d1.y], 1);
        atomicAdd(&g_deg[d1.z], 1);
        atomicAdd(&g_deg[d1.w], 1);
    } else {
        for (int i = e; i < E; i++) atomicAdd(&g_deg[dst[i]], 1);
    }
}

__global__ void blocksum_kernel(int N) {
    __shared__ int sred[SCAN_TB];
    int i = blockIdx.x * SCAN_TB + threadIdx.x;
    int d = (i < N) ? g_deg[i] : 0;
    sred[threadIdx.x] = d;
    __syncthreads();
    for (int off = SCAN_TB / 2; off > 0; off >>= 1) {
        if (threadIdx.x < off) sred[threadIdx.x] += sred[threadIdx.x + off];
        __syncthreads();
    }
    if (threadIdx.x == 0) g_bsum[blockIdx.x] = sred[0];
}

__global__ void scan_bsums_kernel(int nb) {
    __shared__ int s[128];
    int v = (threadIdx.x < nb) ? g_bsum[threadIdx.x] : 0;
    s[threadIdx.x] = v;
    __syncthreads();
    for (int off = 1; off < 128; off <<= 1) {
        int t = (threadIdx.x >= off) ? s[threadIdx.x - off] : 0;
        __syncthreads();
        s[threadIdx.x] += t;
        __syncthreads();
    }
    if (threadIdx.x < nb) g_bsum[threadIdx.x] = s[threadIdx.x] - v;
}

__global__ void starts_kernel(int N) {
    __shared__ int stmp[SCAN_TB];
    int i = blockIdx.x * SCAN_TB + threadIdx.x;
    int d = (i < N) ? g_deg[i] : 0;
    stmp[threadIdx.x] = d;
    __syncthreads();
    for (int off = 1; off < SCAN_TB; off <<= 1) {
        int v = (threadIdx.x >= off) ? stmp[threadIdx.x - off] : 0;
        __syncthreads();
        stmp[threadIdx.x] += v;
        __syncthreads();
    }
    if (i < N) {
        int excl = stmp[threadIdx.x] - d + g_bsum[blockIdx.x];
        g_start[i] = excl;
        g_inv[i] = 1.0f / fmaxf((float)d, 1.0f);
        g_fill[i] = 0;
    }
}

__global__ void place_kernel(const int* __restrict__ src,
                             const int* __restrict__ dst, int E) {
    int t = blockIdx.x * blockDim.x + threadIdx.x;
    int e = t * 8;
    if (e + 8 <= E) {
        int4 d0 = *(const int4*)(dst + e);
        int4 d1 = *(const int4*)(dst + e + 4);
        int4 s0 = *(const int4*)(src + e);
        int4 s1 = *(const int4*)(src + e + 4);
        g_csr[g_start[d0.x] + atomicAdd(&g_fill[d0.x], 1)] = s0.x;
        g_csr[g_start[d0.y] + atomicAdd(&g_fill[d0.y], 1)] = s0.y;
        g_csr[g_start[d0.z] + atomicAdd(&g_fill[d0.z], 1)] = s0.z;
        g_csr[g_start[d0.w] + atomicAdd(&g_fill[d0.w], 1)] = s0.w;
        g_csr[g_start[d1.x] + atomicAdd(&g_fill[d1.x], 1)] = s1.x;
        g_csr[g_start[d1.y] + atomicAdd(&g_fill[d1.y], 1)] = s1.y;
        g_csr[g_start[d1.z] + atomicAdd(&g_fill[d1.z], 1)] = s1.z;
        g_csr[g_start[d1.w] + atomicAdd(&g_fill[d1.w], 1)] = s1.w;
    } else {
        for (int i = e; i < E; i++)
            g_csr[g_start[dst[i]] + atomicAdd(&g_fill[dst[i]], 1)] = src[i];
    }
}

// ---------------- conversions + deg zero (fused) ----------------

__global__ void convert_kernel(const float* __restrict__ x,
                               const float* __restrict__ W1l,
                               const float* __restrict__ W1r,
                               const float* __restrict__ W2l,
                               const float* __restrict__ W2r, int N) {
    int t = blockIdx.x * blockDim.x + threadIdx.x;
    if (t < N) g_deg[t] = 0;
    if (t < N * 32) {
        float2 v = ((const float2*)x)[t];
        g_xh[t] = __floats2half2_rn(v.x, v.y);
    }
    if (t < 4096) g_W1lh[t] = __float2half_rn(W1l[t]);
    else if (t < 8192) g_W1rh[t - 4096] = __float2half_rn(W1r[t - 4096]);
    else if (t < 10240) g_W2lh[t - 8192] = __float2half_rn(W2l[t - 8192]);
    else if (t < 12288) g_W2rh[t - 10240] = __float2half_rn(W2r[t - 10240]);
}

// ---------------- layer-1 gather: warp per node, 4 edges in flight ----------------
// lane = (u = lane>>3: edge slot, lg = lane&7: 16B chunk of the 128B row).
// Unrolled x2: 8 edges per loop iteration. Epilogue: reduce over u via shfl.
__global__ void gather64_warp_kernel(int N) {
    int g = blockIdx.x * blockDim.x + threadIdx.x;
    int node = g >> 5;
    int lane = g & 31;
    if (node >= N) return;
    int u = lane >> 3;
    int lg = lane & 7;
    int s0 = g_start[node];
    int d = g_deg[node];
    const int4* xrow = (const int4*)g_xh;
    float a0 = 0.f, a1 = 0.f, a2 = 0.f, a3 = 0.f;
    float a4 = 0.f, a5 = 0.f, a6 = 0.f, a7 = 0.f;
    for (int j = 0; j < d; j += 8) {
        int e0 = j + u;
        int e1 = j + 4 + u;
        bool p0 = e0 < d, p1 = e1 < d;
        int i0 = p0 ? g_csr[s0 + e0] : 0;
        int i1 = p1 ? g_csr[s0 + e1] : 0;
        int4 v0 = p0 ? xrow[i0 * 8 + lg] : make_int4(0, 0, 0, 0);
        int4 v1 = p1 ? xrow[i1 * 8 + lg] : make_int4(0, 0, 0, 0);
        {
            float2 f0 = __half22float2(*(__half2*)&v0.x);
            float2 f1 = __half22float2(*(__half2*)&v0.y);
            float2 f2 = __half22float2(*(__half2*)&v0.z);
            float2 f3 = __half22float2(*(__half2*)&v0.w);
            a0 += f0.x; a1 += f0.y; a2 += f1.x; a3 += f1.y;
            a4 += f2.x; a5 += f2.y; a6 += f3.x; a7 += f3.y;
        }
        {
            float2 f0 = __half22float2(*(__half2*)&v1.x);
            float2 f1 = __half22float2(*(__half2*)&v1.y);
            float2 f2 = __half22float2(*(__half2*)&v1.z);
            float2 f3 = __half22float2(*(__half2*)&v1.w);
            a0 += f0.x; a1 += f0.y; a2 += f1.x; a3 += f1.y;
            a4 += f2.x; a5 += f2.y; a6 += f3.x; a7 += f3.y;
        }
    }
    // Reduce over edge slots u (lanes lg, lg+8, lg+16, lg+24).
#pragma unroll
    for (int off = 8; off <= 16; off <<= 1) {
        a0 += __shfl_xor_sync(0xffffffffu, a0, off);
        a1 += __shfl_xor_sync(0xffffffffu, a1, off);
        a2 += __shfl_xor_sync(0xffffffffu, a2, off);
        a3 += __shfl_xor_sync(0xffffffffu, a3, off);
        a4 += __shfl_xor_sync(0xffffffffu, a4, off);
        a5 += __shfl_xor_sync(0xffffffffu, a5, off);
        a6 += __shfl_xor_sync(0xffffffffu, a6, off);
        a7 += __shfl_xor_sync(0xffffffffu, a7, off);
    }
    if (u == 0) {
        float iv = g_inv[node];
        __half2 o0 = __floats2half2_rn(a0 * iv, a1 * iv);
        __half2 o1 = __floats2half2_rn(a2 * iv, a3 * iv);
        __half2 o2 = __floats2half2_rn(a4 * iv, a5 * iv);
        __half2 o3 = __floats2half2_rn(a6 * iv, a7 * iv);
        int4 ov;
        ov.x = *(int*)&o0; ov.y = *(int*)&o1; ov.z = *(int*)&o2; ov.w = *(int*)&o3;
        ((int4*)g_mh)[node * 8 + lg] = ov;
    }
}

// ---------------- layer-2: warp per node, 8 edges in flight + fused epilogue ----
// lane = (u = lane>>2: edge slot, lg = lane&3: 16B chunk of 64B row).
__global__ void gather32_fused_kernel(const float* __restrict__ b2,
                                      const float* __restrict__ W3l,
                                      const float* __restrict__ W3r, int N) {
    __shared__ float sb[32], s3l[32], s3r[32];
    if (threadIdx.x < 32) {
        sb[threadIdx.x] = b2[threadIdx.x];
        s3l[threadIdx.x] = W3l[threadIdx.x];
        s3r[threadIdx.x] = W3r[threadIdx.x];
    }
    __syncthreads();
    int g = blockIdx.x * blockDim.x + threadIdx.x;
    int node = g >> 5;
    int lane = g & 31;
    if (node >= N) return;
    int u = lane >> 2;
    int lg = lane & 3;
    int s0 = g_start[node];
    int d = g_deg[node];
    const int4* prow = (const int4*)g_p2;
    float a0 = 0.f, a1 = 0.f, a2 = 0.f, a3 = 0.f;
    float a4 = 0.f, a5 = 0.f, a6 = 0.f, a7 = 0.f;
    for (int j = 0; j < d; j += 16) {
        int e0 = j + u;
        int e1 = j + 8 + u;
        bool p0 = e0 < d, p1 = e1 < d;
        int i0 = p0 ? g_csr[s0 + e0] : 0;
        int i1 = p1 ? g_csr[s0 + e1] : 0;
        int4 v0 = p0 ? prow[i0 * 4 + lg] : make_int4(0, 0, 0, 0);
        int4 v1 = p1 ? prow[i1 * 4 + lg] : make_int4(0, 0, 0, 0);
        {
            float2 f0 = __half22float2(*(__half2*)&v0.x);
            float2 f1 = __half22float2(*(__half2*)&v0.y);
            float2 f2 = __half22float2(*(__half2*)&v0.z);
            float2 f3 = __half22float2(*(__half2*)&v0.w);
            a0 += f0.x; a1 += f0.y; a2 += f1.x; a3 += f1.y;
            a4 += f2.x; a5 += f2.y; a6 += f3.x; a7 += f3.y;
        }
        {
            float2 f0 = __half22float2(*(__half2*)&v1.x);
            float2 f1 = __half22float2(*(__half2*)&v1.y);
            float2 f2 = __half22float2(*(__half2*)&v1.z);
            float2 f3 = __half22float2(*(__half2*)&v1.w);
            a0 += f0.x; a1 += f0.y; a2 += f1.x; a3 += f1.y;
            a4 += f2.x; a5 += f2.y; a6 += f3.x; a7 += f3.y;
        }
    }
    // Reduce over edge slots u (8 slots: xor 4, 8, 16).
#pragma unroll
    for (int off = 4; off <= 16; off <<= 1) {
        a0 += __shfl_xor_sync(0xffffffffu, a0, off);
        a1 += __shfl_xor_sync(0xffffffffu, a1, off);
        a2 += __shfl_xor_sync(0xffffffffu, a2, off);
        a3 += __shfl_xor_sync(0xffffffffu, a3, off);
        a4 += __shfl_xor_sync(0xffffffffu, a4, off);
        a5 += __shfl_xor_sync(0xffffffffu, a5, off);
        a6 += __shfl_xor_sync(0xffffffffu, a6, off);
        a7 += __shfl_xor_sync(0xffffffffu, a7, off);
    }
    // Epilogue on lanes u==0 (lanes 0..3): lane lg owns h2 cols [lg*8, lg*8+8).
    float pa = 0.f, pr = 0.f;
    if (u == 0) {
        float iv = g_inv[node];
        int cb = lg * 8;
        const float4* r2p = (const float4*)(g_r2 + node * 32 + cb);
        float4 r2a = r2p[0], r2b = r2p[1];
        float h[8];
        h[0] = fmaxf(a0 * iv + sb[cb + 0] + r2a.x, 0.f);
        h[1] = fmaxf(a1 * iv + sb[cb + 1] + r2a.y, 0.f);
        h[2] = fmaxf(a2 * iv + sb[cb + 2] + r2a.z, 0.f);
        h[3] = fmaxf(a3 * iv + sb[cb + 3] + r2a.w, 0.f);
        h[4] = fmaxf(a4 * iv + sb[cb + 4] + r2b.x, 0.f);
        h[5] = fmaxf(a5 * iv + sb[cb + 5] + r2b.y, 0.f);
        h[6] = fmaxf(a6 * iv + sb[cb + 6] + r2b.z, 0.f);
        h[7] = fmaxf(a7 * iv + sb[cb + 7] + r2b.w, 0.f);
#pragma unroll
        for (int q = 0; q < 8; q++) {
            pa = fmaf(h[q], s3l[cb + q], pa);
            pr = fmaf(h[q], s3r[cb + q], pr);
        }
    }
    pa += __shfl_xor_sync(0xffffffffu, pa, 1);
    pr += __shfl_xor_sync(0xffffffffu, pr, 1);
    pa += __shfl_xor_sync(0xffffffffu, pa, 2);
    pr += __shfl_xor_sync(0xffffffffu, pr, 2);
    if (lane == 0) {
        g_p3[node] = pa;
        g_r3[node] = pr;
    }
}

// ---------------- tensor-core fused dense chain ----------------

__global__ void dense_wmma_kernel(const float* __restrict__ b1, int N) {
    __shared__ float  sF[64 * 64];
    __shared__ __half sH[64 * 64];
    int warp = threadIdx.x >> 5;
    int base = blockIdx.x * 64;
    const __half* mh = (const __half*)g_mh;
    const __half* xh = (const __half*)g_xh;

    wmma::fragment<wmma::accumulator, 16, 16, 16, float> acc;
    wmma::fragment<wmma::matrix_a, 16, 16, 16, __half, wmma::row_major> fa;
    wmma::fragment<wmma::matrix_b, 16, 16, 16, __half, wmma::row_major> fb;

    int arow = (base + warp * 16) * 64;
#pragma unroll
    for (int nt = 0; nt < 4; nt++) {
        wmma::fill_fragment(acc, 0.f);
#pragma unroll
        for (int k = 0; k < 4; k++) {
            wmma::load_matrix_sync(fa, mh + arow + k * 16, 64);
            wmma::load_matrix_sync(fb, g_W1lh + (k * 16) * 64 + nt * 16, 64);
            wmma::mma_sync(acc, fa, fb, acc);
            wmma::load_matrix_sync(fa, xh + arow + k * 16, 64);
            wmma::load_matrix_sync(fb, g_W1rh + (k * 16) * 64 + nt * 16, 64);
            wmma::mma_sync(acc, fa, fb, acc);
        }
        wmma::store_matrix_sync(sF + (warp * 16) * 64 + nt * 16, acc, 64, wmma::mem_row_major);
    }
    __syncthreads();
    for (int i = threadIdx.x; i < 64 * 64; i += blockDim.x) {
        int col = i & 63;
        sH[i] = __float2half_rn(fmaxf(sF[i] + b1[col], 0.f));
    }
    __syncthreads();

#pragma unroll
    for (int nt = 0; nt < 2; nt++) {
        wmma::fill_fragment(acc, 0.f);
#pragma unroll
        for (int k = 0; k < 4; k++) {
            wmma::load_matrix_sync(fa, sH + (warp * 16) * 64 + k * 16, 64);
            wmma::load_matrix_sync(fb, g_W2lh + (k * 16) * 32 + nt * 16, 32);
            wmma::mma_sync(acc, fa, fb, acc);
        }
        wmma::store_matrix_sync(sF + (warp * 16) * 32 + nt * 16, acc, 32, wmma::mem_row_major);
    }
    __syncthreads();
    for (int i = threadIdx.x; i < 64 * 32; i += blockDim.x) {
        int node = base + (i >> 5);
        if (node < N) ((__half*)g_p2)[node * 32 + (i & 31)] = __float2half_rn(sF[i]);
    }
    __syncthreads();

#pragma unroll
    for (int nt = 0; nt < 2; nt++) {
        wmma::fill_fragment(acc, 0.f);
#pragma unroll
        for (int k = 0; k < 4; k++) {
            wmma::load_matrix_sync(fa, sH + (warp * 16) * 64 + k * 16, 64);
            wmma::load_matrix_sync(fb, g_W2rh + (k * 16) * 32 + nt * 16, 32);
            wmma::mma_sync(acc, fa, fb, acc);
        }
        wmma::store_matrix_sync(sF + (warp * 16) * 32 + nt * 16, acc, 32, wmma::mem_row_major);
    }
    __syncthreads();
    for (int i = threadIdx.x; i < 64 * 32; i += blockDim.x) {
        int node = base + (i >> 5);
        if (node < N) g_r2[node * 32 + (i & 31)] = sF[i];
    }
}

// Final: one warp per node, lanes parallel over edges; fused sigmoid.
__global__ void gather1_final_kernel(const float* __restrict__ b3,
                                     float* __restrict__ out, int N) {
    int g = blockIdx.x * blockDim.x + threadIdx.x;
    int node = g >> 5;
    int lane = g & 31;
    if (node >= N) return;
    int s0 = g_start[node];
    int d = g_deg[node];
    float acc = 0.f;
    for (int j = lane; j < d; j += 32) acc += g_p3[g_csr[s0 + j]];
#pragma unroll
    for (int off = 16; off; off >>= 1) acc += __shfl_xor_sync(0xffffffffu, acc, off);
    if (lane == 0) {
        float v = acc * g_inv[node] + b3[0] + g_r3[node];
        out[node] = 1.0f / (1.0f + expf(-v));
    }
}

// ---------------- launch ----------------

extern "C" void kernel_launch(void* const* d_in, const int* in_sizes, int n_in,
                              void* d_out, int out_size) {
    const float* x   = (const float*)d_in[0];
    const int*   ei  = (const int*)d_in[1];   // int32 (JAX x64 disabled)
    const float* W1l = (const float*)d_in[2];
    const float* b1  = (const float*)d_in[3];
    const float* W1r = (const float*)d_in[4];
    const float* W2l = (const float*)d_in[5];
    const float* b2  = (const float*)d_in[6];
    const float* W2r = (const float*)d_in[7];
    const float* W3l = (const float*)d_in[8];
    const float* b3  = (const float*)d_in[9];
    const float* W3r = (const float*)d_in[10];
    float* out = (float*)d_out;

    int N = in_sizes[0] / 64;
    int E = in_sizes[1] / 2;
    const int* src = ei;
    const int* dst = ei + E;

    const int TB = 256;
    auto blocks = [](long long n, int tb) { return (int)((n + tb - 1) / tb); };
    int nb = (N + SCAN_TB - 1) / SCAN_TB;
    int E8 = (E + 7) / 8;

    convert_kernel<<<blocks((long long)N * 32, TB), TB>>>(x, W1l, W1r, W2l, W2r, N);
    hist_kernel<<<blocks(E8, TB), TB>>>(dst, E);
    blocksum_kernel<<<nb, SCAN_TB>>>(N);
    scan_bsums_kernel<<<1, 128>>>(nb);
    starts_kernel<<<nb, SCAN_TB>>>(N);
    place_kernel<<<blocks(E8, TB), TB>>>(src, dst, E);

    gather64_warp_kernel<<<blocks((long long)N * 32, TB), TB>>>(N);
    dense_wmma_kernel<<<(N + 63) / 64, 128>>>(b1, N);
    gather32_fused_kernel<<<blocks((long long)N * 32, TB), TB>>>(b2, W3l, W3r, N);
    gather1_final_kernel<<<blocks((long long)N * 32, TB), TB>>>(b3, out, N);
}

// round 16
// speedup vs baseline: 1.0400x; 1.0400x over previous
#include <cuda_runtime.h>
#include <cuda_fp16.h>
#include <mma.h>
#include <math.h>

using namespace nvcuda;

// GraphSAGE 3-layer, N=100000, E=3200000, D: 64 -> 64 -> 32 -> 1
// R16: R13 gather design (best) + scan_bsums folded into starts +
// dense_wmma widened to 128 nodes/block.

#define NMAX 100000
#define NPAD 100096
#define EMAX 3200000
#define SCAN_TB 1024

__device__ __align__(16) __half2 g_xh[NPAD * 32];   // x in fp16 (64 per node)
__device__ __align__(16) __half2 g_mh[NPAD * 32];   // layer-1 mean in fp16
__device__ __align__(16) __half2 g_p2[NPAD * 16];   // h1@W2l in fp16 (32 per node)
__device__ __align__(16) float   g_r2[NMAX * 32];   // h1@W2r in fp32 (self term)
__device__ __half g_W1lh[64 * 64];
__device__ __half g_W1rh[64 * 64];
__device__ __half g_W2lh[64 * 32];
__device__ __half g_W2rh[64 * 32];
__device__ float g_p3[NMAX];
__device__ float g_r3[NMAX];
__device__ float g_inv[NMAX];
__device__ int   g_deg[NMAX];
__device__ int   g_start[NMAX];
__device__ int   g_fill[NMAX];
__device__ int   g_bsum[128];
__device__ int   g_csr[EMAX];

// ---------------- CSR build ----------------

__global__ void hist_kernel(const int* __restrict__ dst, int E) {
    int t = blockIdx.x * blockDim.x + threadIdx.x;
    int e = t * 8;
    if (e + 8 <= E) {
        int4 d0 = *(const int4*)(dst + e);
        int4 d1 = *(const int4*)(dst + e + 4);
        atomicAdd(&g_deg[d0.x], 1);
        atomicAdd(&g_deg[d0.y], 1);
        atomicAdd(&g_deg[d0.z], 1);
        atomicAdd(&g_deg[d0.w], 1);
        atomicAdd(&g_deg[d1.x], 1);
        atomicAdd(&g_deg[d1.y], 1);
        atomicAdd(&g_deg[d1.z], 1);
        atomicAdd(&g_deg[d1.w], 1);
    } else {
        for (int i = e; i < E; i++) atomicAdd(&g_deg[dst[i]], 1);
    }
}

__global__ void blocksum_kernel(int N) {
    __shared__ int sred[SCAN_TB];
    int i = blockIdx.x * SCAN_TB + threadIdx.x;
    int d = (i < N) ? g_deg[i] : 0;
    sred[threadIdx.x] = d;
    __syncthreads();
    for (int off = SCAN_TB / 2; off > 0; off >>= 1) {
        if (threadIdx.x < off) sred[threadIdx.x] += sred[threadIdx.x + off];
        __syncthreads();
    }
    if (threadIdx.x == 0) g_bsum[blockIdx.x] = sred[0];
}

// starts: per-block scan of degrees; block offset computed locally from g_bsum
// (<=128 entries, scanned in smem by every block — no separate scan kernel).
__global__ void starts_kernel(int N, int nb) {
    __shared__ int stmp[SCAN_TB];
    __shared__ int sbs[128];
    if (threadIdx.x < 128)
        sbs[threadIdx.x] = (threadIdx.x < nb) ? g_bsum[threadIdx.x] : 0;
    __syncthreads();
    for (int off = 1; off < 128; off <<= 1) {
        int v = 0;
        if (threadIdx.x < 128 && threadIdx.x >= off) v = sbs[threadIdx.x - off];
        __syncthreads();
        if (threadIdx.x < 128) sbs[threadIdx.x] += v;
        __syncthreads();
    }
    int blockoff = (blockIdx.x == 0) ? 0 : sbs[blockIdx.x - 1];

    int i = blockIdx.x * SCAN_TB + threadIdx.x;
    int d = (i < N) ? g_deg[i] : 0;
    stmp[threadIdx.x] = d;
    __syncthreads();
    for (int off = 1; off < SCAN_TB; off <<= 1) {
        int v = (threadIdx.x >= off) ? stmp[threadIdx.x - off] : 0;
        __syncthreads();
        stmp[threadIdx.x] += v;
        __syncthreads();
    }
    if (i < N) {
        int excl = stmp[threadIdx.x] - d + blockoff;
        g_start[i] = excl;
        g_inv[i] = 1.0f / fmaxf((float)d, 1.0f);
        g_fill[i] = 0;
    }
}

__global__ void place_kernel(const int* __restrict__ src,
                             const int* __restrict__ dst, int E) {
    int t = blockIdx.x * blockDim.x + threadIdx.x;
    int e = t * 8;
    if (e + 8 <= E) {
        int4 d0 = *(const int4*)(dst + e);
        int4 d1 = *(const int4*)(dst + e + 4);
        int4 s0 = *(const int4*)(src + e);
        int4 s1 = *(const int4*)(src + e + 4);
        g_csr[g_start[d0.x] + atomicAdd(&g_fill[d0.x], 1)] = s0.x;
        g_csr[g_start[d0.y] + atomicAdd(&g_fill[d0.y], 1)] = s0.y;
        g_csr[g_start[d0.z] + atomicAdd(&g_fill[d0.z], 1)] = s0.z;
        g_csr[g_start[d0.w] + atomicAdd(&g_fill[d0.w], 1)] = s0.w;
        g_csr[g_start[d1.x] + atomicAdd(&g_fill[d1.x], 1)] = s1.x;
        g_csr[g_start[d1.y] + atomicAdd(&g_fill[d1.y], 1)] = s1.y;
        g_csr[g_start[d1.z] + atomicAdd(&g_fill[d1.z], 1)] = s1.z;
        g_csr[g_start[d1.w] + atomicAdd(&g_fill[d1.w], 1)] = s1.w;
    } else {
        for (int i = e; i < E; i++)
            g_csr[g_start[dst[i]] + atomicAdd(&g_fill[dst[i]], 1)] = src[i];
    }
}

// ---------------- conversions + deg zero (fused) ----------------

__global__ void convert_kernel(const float* __restrict__ x,
                               const float* __restrict__ W1l,
                               const float* __restrict__ W1r,
                               const float* __restrict__ W2l,
                               const float* __restrict__ W2r, int N) {
    int t = blockIdx.x * blockDim.x + threadIdx.x;
    if (t < N) g_deg[t] = 0;
    if (t < N * 32) {
        float2 v = ((const float2*)x)[t];
        g_xh[t] = __floats2half2_rn(v.x, v.y);
    }
    if (t < 4096) g_W1lh[t] = __float2half_rn(W1l[t]);
    else if (t < 8192) g_W1rh[t - 4096] = __float2half_rn(W1r[t - 4096]);
    else if (t < 10240) g_W2lh[t - 8192] = __float2half_rn(W2l[t - 8192]);
    else if (t < 12288) g_W2rh[t - 10240] = __float2half_rn(W2r[t - 10240]);
}

// ---------------- layer-1 gather (R13 design: 4 nodes/warp, 8 lanes/node) ----

__global__ void gather64_v4_kernel(int N) {
    int g = blockIdx.x * blockDim.x + threadIdx.x;
    int warp = g >> 5;
    int lane = g & 31;
    int node = warp * 4 + (lane >> 3);
    int lg = lane & 7;
    if (node >= N) return;
    int s0 = g_start[node];
    int d = g_deg[node];
    const int4* xrow = (const int4*)g_xh;
    float a0 = 0.f, a1 = 0.f, a2 = 0.f, a3 = 0.f;
    float a4 = 0.f, a5 = 0.f, a6 = 0.f, a7 = 0.f;
    int j = 0;
    for (; j + 4 <= d; j += 4) {
        int si[4];
#pragma unroll
        for (int u = 0; u < 4; u++) si[u] = g_csr[s0 + j + u];
        int4 v[4];
#pragma unroll
        for (int u = 0; u < 4; u++) v[u] = xrow[si[u] * 8 + lg];
#pragma unroll
        for (int u = 0; u < 4; u++) {
            float2 f0 = __half22float2(*(__half2*)&v[u].x);
            float2 f1 = __half22float2(*(__half2*)&v[u].y);
            float2 f2 = __half22float2(*(__half2*)&v[u].z);
            float2 f3 = __half22float2(*(__half2*)&v[u].w);
            a0 += f0.x; a1 += f0.y; a2 += f1.x; a3 += f1.y;
            a4 += f2.x; a5 += f2.y; a6 += f3.x; a7 += f3.y;
        }
    }
    for (; j < d; j++) {
        int4 v = xrow[g_csr[s0 + j] * 8 + lg];
        float2 f0 = __half22float2(*(__half2*)&v.x);
        float2 f1 = __half22float2(*(__half2*)&v.y);
        float2 f2 = __half22float2(*(__half2*)&v.z);
        float2 f3 = __half22float2(*(__half2*)&v.w);
        a0 += f0.x; a1 += f0.y; a2 += f1.x; a3 += f1.y;
        a4 += f2.x; a5 += f2.y; a6 += f3.x; a7 += f3.y;
    }
    float iv = g_inv[node];
    __half2 o0 = __floats2half2_rn(a0 * iv, a1 * iv);
    __half2 o1 = __floats2half2_rn(a2 * iv, a3 * iv);
    __half2 o2 = __floats2half2_rn(a4 * iv, a5 * iv);
    __half2 o3 = __floats2half2_rn(a6 * iv, a7 * iv);
    int4 ov;
    ov.x = *(int*)&o0; ov.y = *(int*)&o1; ov.z = *(int*)&o2; ov.w = *(int*)&o3;
    ((int4*)g_mh)[node * 8 + lg] = ov;
}

// ---------------- layer-2 gather + combine + layer-3 dots (R13 design) ----------

__global__ void gather32_fused_kernel(const float* __restrict__ b2,
                                      const float* __restrict__ W3l,
                                      const float* __restrict__ W3r, int N) {
    __shared__ float sb[32], s3l[32], s3r[32];
    if (threadIdx.x < 32) {
        sb[threadIdx.x] = b2[threadIdx.x];
        s3l[threadIdx.x] = W3l[threadIdx.x];
        s3r[threadIdx.x] = W3r[threadIdx.x];
    }
    __syncthreads();
    int g = blockIdx.x * blockDim.x + threadIdx.x;
    int warp = g >> 5;
    int lane = g & 31;
    int node = warp * 8 + (lane >> 2);
    int lg = lane & 3;
    if (node >= N) return;
    int s0 = g_start[node];
    int d = g_deg[node];
    const int4* prow = (const int4*)g_p2;
    float a0 = 0.f, a1 = 0.f, a2 = 0.f, a3 = 0.f;
    float a4 = 0.f, a5 = 0.f, a6 = 0.f, a7 = 0.f;
    int j = 0;
    for (; j + 4 <= d; j += 4) {
        int si[4];
#pragma unroll
        for (int u = 0; u < 4; u++) si[u] = g_csr[s0 + j + u];
        int4 v[4];
#pragma unroll
        for (int u = 0; u < 4; u++) v[u] = prow[si[u] * 4 + lg];
#pragma unroll
        for (int u = 0; u < 4; u++) {
            float2 f0 = __half22float2(*(__half2*)&v[u].x);
            float2 f1 = __half22float2(*(__half2*)&v[u].y);
            float2 f2 = __half22float2(*(__half2*)&v[u].z);
            float2 f3 = __half22float2(*(__half2*)&v[u].w);
            a0 += f0.x; a1 += f0.y; a2 += f1.x; a3 += f1.y;
            a4 += f2.x; a5 += f2.y; a6 += f3.x; a7 += f3.y;
        }
    }
    for (; j < d; j++) {
        int4 v = prow[g_csr[s0 + j] * 4 + lg];
        float2 f0 = __half22float2(*(__half2*)&v.x);
        float2 f1 = __half22float2(*(__half2*)&v.y);
        float2 f2 = __half22float2(*(__half2*)&v.z);
        float2 f3 = __half22float2(*(__half2*)&v.w);
        a0 += f0.x; a1 += f0.y; a2 += f1.x; a3 += f1.y;
        a4 += f2.x; a5 += f2.y; a6 += f3.x; a7 += f3.y;
    }
    float iv = g_inv[node];
    int cb = lg * 8;
    const float4* r2p = (const float4*)(g_r2 + node * 32 + cb);
    float4 r2a = r2p[0], r2b = r2p[1];
    float h[8];
    h[0] = fmaxf(a0 * iv + sb[cb + 0] + r2a.x, 0.f);
    h[1] = fmaxf(a1 * iv + sb[cb + 1] + r2a.y, 0.f);
    h[2] = fmaxf(a2 * iv + sb[cb + 2] + r2a.z, 0.f);
    h[3] = fmaxf(a3 * iv + sb[cb + 3] + r2a.w, 0.f);
    h[4] = fmaxf(a4 * iv + sb[cb + 4] + r2b.x, 0.f);
    h[5] = fmaxf(a5 * iv + sb[cb + 5] + r2b.y, 0.f);
    h[6] = fmaxf(a6 * iv + sb[cb + 6] + r2b.z, 0.f);
    h[7] = fmaxf(a7 * iv + sb[cb + 7] + r2b.w, 0.f);
    float pa = 0.f, pr = 0.f;
#pragma unroll
    for (int q = 0; q < 8; q++) {
        pa = fmaf(h[q], s3l[cb + q], pa);
        pr = fmaf(h[q], s3r[cb + q], pr);
    }
    unsigned m = __activemask();
    pa += __shfl_xor_sync(m, pa, 1);
    pr += __shfl_xor_sync(m, pr, 1);
    pa += __shfl_xor_sync(m, pa, 2);
    pr += __shfl_xor_sync(m, pr, 2);
    if (lg == 0) {
        g_p3[node] = pa;
        g_r3[node] = pr;
    }
}

// ---------------- tensor-core fused dense chain (128 nodes / 256 thr) ----------

__global__ void dense_wmma_kernel(const float* __restrict__ b1, int N) {
    __shared__ float  sF[128 * 64];   // 32KB
    __shared__ __half sH[128 * 64];   // 16KB
    int warp = threadIdx.x >> 5;      // 0..7
    int base = blockIdx.x * 128;
    const __half* mh = (const __half*)g_mh;
    const __half* xh = (const __half*)g_xh;

    wmma::fragment<wmma::accumulator, 16, 16, 16, float> acc;
    wmma::fragment<wmma::matrix_a, 16, 16, 16, __half, wmma::row_major> fa;
    wmma::fragment<wmma::matrix_b, 16, 16, 16, __half, wmma::row_major> fb;

    int arow = (base + warp * 16) * 64;
#pragma unroll
    for (int nt = 0; nt < 4; nt++) {
        wmma::fill_fragment(acc, 0.f);
#pragma unroll
        for (int k = 0; k < 4; k++) {
            wmma::load_matrix_sync(fa, mh + arow + k * 16, 64);
            wmma::load_matrix_sync(fb, g_W1lh + (k * 16) * 64 + nt * 16, 64);
            wmma::mma_sync(acc, fa, fb, acc);
            wmma::load_matrix_sync(fa, xh + arow + k * 16, 64);
            wmma::load_matrix_sync(fb, g_W1rh + (k * 16) * 64 + nt * 16, 64);
            wmma::mma_sync(acc, fa, fb, acc);
        }
        wmma::store_matrix_sync(sF + (warp * 16) * 64 + nt * 16, acc, 64, wmma::mem_row_major);
    }
    __syncthreads();
    for (int i = threadIdx.x; i < 128 * 64; i += blockDim.x) {
        int col = i & 63;
        sH[i] = __float2half_rn(fmaxf(sF[i] + b1[col], 0.f));
    }
    __syncthreads();

#pragma unroll
    for (int nt = 0; nt < 2; nt++) {
        wmma::fill_fragment(acc, 0.f);
#pragma unroll
        for (int k = 0; k < 4; k++) {
            wmma::load_matrix_sync(fa, sH + (warp * 16) * 64 + k * 16, 64);
            wmma::load_matrix_sync(fb, g_W2lh + (k * 16) * 32 + nt * 16, 32);
            wmma::mma_sync(acc, fa, fb, acc);
        }
        wmma::store_matrix_sync(sF + (warp * 16) * 32 + nt * 16, acc, 32, wmma::mem_row_major);
    }
    __syncthreads();
    for (int i = threadIdx.x; i < 128 * 32; i += blockDim.x) {
        int node = base + (i >> 5);
        if (node < N) ((__half*)g_p2)[node * 32 + (i & 31)] = __float2half_rn(sF[i]);
    }
    __syncthreads();

#pragma unroll
    for (int nt = 0; nt < 2; nt++) {
        wmma::fill_fragment(acc, 0.f);
#pragma unroll
        for (int k = 0; k < 4; k++) {
            wmma::load_matrix_sync(fa, sH + (warp * 16) * 64 + k * 16, 64);
            wmma::load_matrix_sync(fb, g_W2rh + (k * 16) * 32 + nt * 16, 32);
            wmma::mma_sync(acc, fa, fb, acc);
        }
        wmma::store_matrix_sync(sF + (warp * 16) * 32 + nt * 16, acc, 32, wmma::mem_row_major);
    }
    __syncthreads();
    for (int i = threadIdx.x; i < 128 * 32; i += blockDim.x) {
        int node = base + (i >> 5);
        if (node < N) g_r2[node * 32 + (i & 31)] = sF[i];
    }
}

// Final: one warp per node, lanes parallel over edges; fused sigmoid.
__global__ void gather1_final_kernel(const float* __restrict__ b3,
                                     float* __restrict__ out, int N) {
    int g = blockIdx.x * blockDim.x + threadIdx.x;
    int node = g >> 5;
    int lane = g & 31;
    if (node >= N) return;
    int s0 = g_start[node];
    int d = g_deg[node];
    float acc = 0.f;
    for (int j = lane; j < d; j += 32) acc += g_p3[g_csr[s0 + j]];
#pragma unroll
    for (int off = 16; off; off >>= 1) acc += __shfl_xor_sync(0xffffffffu, acc, off);
    if (lane == 0) {
        float v = acc * g_inv[node] + b3[0] + g_r3[node];
        out[node] = 1.0f / (1.0f + expf(-v));
    }
}

// ---------------- launch ----------------

extern "C" void kernel_launch(void* const* d_in, const int* in_sizes, int n_in,
                              void* d_out, int out_size) {
    const float* x   = (const float*)d_in[0];
    const int*   ei  = (const int*)d_in[1];   // int32 (JAX x64 disabled)
    const float* W1l = (const float*)d_in[2];
    const float* b1  = (const float*)d_in[3];
    const float* W1r = (const float*)d_in[4];
    const float* W2l = (const float*)d_in[5];
    const float* b2  = (const float*)d_in[6];
    const float* W2r = (const float*)d_in[7];
    const float* W3l = (const float*)d_in[8];
    const float* b3  = (const float*)d_in[9];
    const float* W3r = (const float*)d_in[10];
    float* out = (float*)d_out;

    int N = in_sizes[0] / 64;
    int E = in_sizes[1] / 2;
    const int* src = ei;
    const int* dst = ei + E;

    const int TB = 256;
    auto blocks = [](long long n, int tb) { return (int)((n + tb - 1) / tb); };
    int nb = (N + SCAN_TB - 1) / SCAN_TB;
    int E8 = (E + 7) / 8;

    convert_kernel<<<blocks((long long)N * 32, TB), TB>>>(x, W1l, W1r, W2l, W2r, N);
    hist_kernel<<<blocks(E8, TB), TB>>>(dst, E);
    blocksum_kernel<<<nb, SCAN_TB>>>(N);
    starts_kernel<<<nb, SCAN_TB>>>(N, nb);
    place_kernel<<<blocks(E8, TB), TB>>>(src, dst, E);

    gather64_v4_kernel<<<blocks((long long)N * 8, TB), TB>>>(N);
    dense_wmma_kernel<<<(N + 127) / 128, 256>>>(b1, N);
    gather32_fused_kernel<<<blocks((long long)N * 4, TB), TB>>>(b2, W3l, W3r, N);
    gather1_final_kernel<<<blocks((long long)N * 32, TB), TB>>>(b3, out, N);
}